// round 14
// baseline (speedup 1.0000x reference)
#include <cuda_runtime.h>
#include <cuda_fp16.h>
#include <cstdint>

// N=100000, E=1600000, D=8, K=1, C=32 (dims from in_sizes at runtime).
#define MAXN 100352
#define MAXE 1638400
#define SCAN_BLK 1024
#define MAX_SB 128   // max scan blocks (ceil(MAXN/1024) = 98)

__device__ __align__(16) __half g_xgh[MAXN * 32];    // x @ g (fp16 gather payload)
__device__ __align__(16) float g_rootb[MAXN * 32];   // root term (layer 1)
__device__ __align__(16) float g_rootb2[MAXN * 32];  // root term (layer 2)
__device__ __align__(16) float g_h[MAXN * 32];       // layer-1 output (fp32)
__device__ __align__(16) uint2 g_edges[MAXE];        // (src, half2(gau1,gau2)) sorted by dst
__device__ int g_cnt[MAXN];                           // in-degree histogram
__device__ int g_rowptr[MAXN + 1];                    // CSR row pointers (by dst)
__device__ int g_cursor[MAXN];                        // scatter cursors
__device__ int g_bsum[MAX_SB];                        // scan block sums

// ---------------- CSR build ----------------

__global__ void __launch_bounds__(256) hist_k(const int* __restrict__ ei, int* __restrict__ cnt, int E) {
    int e = blockIdx.x * blockDim.x + threadIdx.x;
    if (e < E) atomicAdd(cnt + __ldg(ei + E + e), 1);
}

// Per-block exclusive scan of 1024 counts; block totals to bsum.
__global__ void __launch_bounds__(SCAN_BLK) scan1_k(const int* __restrict__ cnt,
                                                    int* __restrict__ rowptr,
                                                    int* __restrict__ bsum, int N) {
    __shared__ int sh[SCAN_BLK];
    int t = threadIdx.x;
    int i = blockIdx.x * SCAN_BLK + t;
    int v = (i < N) ? cnt[i] : 0;
    sh[t] = v;
    __syncthreads();
    for (int off = 1; off < SCAN_BLK; off <<= 1) {
        int add = (t >= off) ? sh[t - off] : 0;
        __syncthreads();
        sh[t] += add;
        __syncthreads();
    }
    if (i < N) rowptr[i] = sh[t] - v;  // exclusive
    if (t == SCAN_BLK - 1) bsum[blockIdx.x] = sh[t];
}

// Fused scan2+scan3: each block computes its own block-offset (warp-reduced
// prefix over <=98 block sums), then applies it and initializes cursors.
__global__ void __launch_bounds__(SCAN_BLK) scan23_k(int* __restrict__ rowptr,
                                                     int* __restrict__ cursor,
                                                     const int* __restrict__ bsum,
                                                     int N, int E) {
    __shared__ int s_off;
    int t = threadIdx.x;
    if (t < 32) {
        int acc = 0;
        for (int j = t; j < blockIdx.x; j += 32) acc += __ldg(bsum + j);
        acc += __shfl_xor_sync(0xffffffffu, acc, 16);
        acc += __shfl_xor_sync(0xffffffffu, acc, 8);
        acc += __shfl_xor_sync(0xffffffffu, acc, 4);
        acc += __shfl_xor_sync(0xffffffffu, acc, 2);
        acc += __shfl_xor_sync(0xffffffffu, acc, 1);
        if (t == 0) s_off = acc;
    }
    __syncthreads();
    int i = blockIdx.x * SCAN_BLK + t;
    if (i < N) {
        int v = rowptr[i] + s_off;
        rowptr[i] = v;
        cursor[i] = v;
    }
    if (i == 0) rowptr[N] = E;
}

// Gaussian weights (both layers, packed half2) + scatter 8B records to the
// dst-sorted slot.
__global__ void __launch_bounds__(256) gau_scatter_k(
    const int* __restrict__ ei,
    const float4* __restrict__ ea,    // [E,8] viewed as [E,2] float4
    const float* __restrict__ mu1, const float* __restrict__ s1,
    const float* __restrict__ mu2, const float* __restrict__ s2,
    int* __restrict__ cursor,
    uint2* __restrict__ edges, int E) {
    int e = blockIdx.x * blockDim.x + threadIdx.x;
    if (e >= E) return;
    float4 a = ea[e * 2];
    float4 b = ea[e * 2 + 1];
    float v[8] = {a.x, a.y, a.z, a.w, b.x, b.y, b.z, b.w};
    float t1 = 0.f, t2 = 0.f;
#pragma unroll
    for (int d = 0; d < 8; d++) {
        float d1 = v[d] - __ldg(mu1 + d);
        float d2 = v[d] - __ldg(mu2 + d);
        t1 += (-0.5f * d1 * d1) / (1e-15f + __ldg(s1 + d) * __ldg(s1 + d));
        t2 += (-0.5f * d2 * d2) / (1e-15f + __ldg(s2 + d) * __ldg(s2 + d));
    }
    int src = __ldg(ei + e);
    int dst = __ldg(ei + E + e);
    int pos = atomicAdd(cursor + dst, 1);
    __half2 gp = __floats2half2_rn(__expf(t1), __expf(t2));
    uint2 rec;
    rec.x = (unsigned)src;
    rec.y = *reinterpret_cast<unsigned*>(&gp);
    edges[pos] = rec;
}

// ---------------- GEMM (register weights, fp16 xg output, 2-row ILP) ----------------
// Each warp processes TWO rows per iteration (r and r+8): four independent
// accumulator chains overlap the broadcast-LDS latency that binds the 1-row
// version at reg-limited occupancy.
__global__ void __launch_bounds__(256) gemm_k(
    const float* __restrict__ xin,
    const float* __restrict__ g,
    const float* __restrict__ root,
    const float* __restrict__ bias,
    __half* __restrict__ xg,
    float* __restrict__ rb_out,
    int N) {
    __shared__ float sx[128][32];
    const int t = threadIdx.x;
    const int lane = t & 31;
    const int w = t >> 5;

    float wg[32], wr[32];
#pragma unroll
    for (int k = 0; k < 32; k++) {
        wg[k] = __ldg(g + k * 32 + lane);
        wr[k] = __ldg(root + k * 32 + lane);
    }
    const float bv = __ldg(bias + lane);

    const int base = blockIdx.x * 128;
    const int nrows = min(128, N - base);

    for (int i = t; i < nrows * 32; i += 256)
        sx[i >> 5][i & 31] = xin[(size_t)base * 32 + i];
    __syncthreads();

    for (int r = w; r < nrows; r += 16) {
        const int r2 = r + 8;
        const bool has2 = (r2 < nrows);
        const int r2c = has2 ? r2 : r;
        float a0 = 0.0f, b0 = bv;
        float a1 = 0.0f, b1 = bv;
#pragma unroll
        for (int k = 0; k < 32; k++) {
            float x0 = sx[r][k];
            float x1 = sx[r2c][k];
            a0 = fmaf(x0, wg[k], a0);
            b0 = fmaf(x0, wr[k], b0);
            a1 = fmaf(x1, wg[k], a1);
            b1 = fmaf(x1, wr[k], b1);
        }
        size_t o0 = (size_t)(base + r) * 32 + lane;
        xg[o0] = __float2half_rn(a0);
        rb_out[o0] = b0;
        if (has2) {
            size_t o1 = (size_t)(base + r2) * 32 + lane;
            xg[o1] = __float2half_rn(a1);
            rb_out[o1] = b1;
        }
    }
}

// ---------------- Pull aggregation: 2 edges per warp-instruction ----------------
// One warp per dst node. Lanes 0-15 process edge A, lanes 16-31 edge B; each
// lane owns 2 channels as one __half2 (4B load). Records loaded coalesced,
// redistributed via shfl; epilogue folds half-warps with shfl_xor(16).
template <int LAYER>
__global__ void __launch_bounds__(256) pull_k(
    const int* __restrict__ rowptr,
    const uint2* __restrict__ edges,
    const __half2* __restrict__ xg,   // [N,16] half2 rows
    const float2* __restrict__ rootb, // [N,16] float2 rows
    float2* __restrict__ out,         // [N,16] float2 rows
    int N) {
    int warp = (blockIdx.x * blockDim.x + threadIdx.x) >> 5;
    int lane = threadIdx.x & 31;
    if (warp >= N) return;

    const int c2 = lane & 15;     // channel-pair index (channels 2*c2, 2*c2+1)
    const int which = lane >> 4;  // 0 -> even edge, 1 -> odd edge

    int s = __ldg(rowptr + warp);
    int e = __ldg(rowptr + warp + 1);
    int deg = e - s;

    float ax0 = 0.f, ay0 = 0.f, ax1 = 0.f, ay1 = 0.f;

    for (int j = s; j < e; j += 32) {
        int m = min(32, e - j);
        // cooperative coalesced record load: lane i -> record j+i
        int   si = 0;
        float gv = 0.f;
        if (lane < m) {
            uint2 r = edges[j + lane];
            si = (int)r.x;
            __half2 gp = *reinterpret_cast<__half2*>(&r.y);
            gv = (LAYER == 1) ? __low2float(gp) : __high2float(gp);
        }
        int k = 0;
        for (; k + 4 <= m; k += 4) {
            int   sa = __shfl_sync(0xffffffffu, si, k + which);
            float ga = __shfl_sync(0xffffffffu, gv, k + which);
            int   sb = __shfl_sync(0xffffffffu, si, k + 2 + which);
            float gb = __shfl_sync(0xffffffffu, gv, k + 2 + which);
            float2 xa = __half22float2(__ldg(xg + (size_t)sa * 16 + c2));
            float2 xb = __half22float2(__ldg(xg + (size_t)sb * 16 + c2));
            ax0 = fmaf(ga, xa.x, ax0);
            ay0 = fmaf(ga, xa.y, ay0);
            ax1 = fmaf(gb, xb.x, ax1);
            ay1 = fmaf(gb, xb.y, ay1);
        }
        for (; k + 2 <= m; k += 2) {
            int   sa = __shfl_sync(0xffffffffu, si, k + which);
            float ga = __shfl_sync(0xffffffffu, gv, k + which);
            float2 xa = __half22float2(__ldg(xg + (size_t)sa * 16 + c2));
            ax0 = fmaf(ga, xa.x, ax0);
            ay0 = fmaf(ga, xa.y, ay0);
        }
        if (k < m) {  // single leftover edge: only the 'which==0' half contributes
            int   sa = __shfl_sync(0xffffffffu, si, k);
            float ga = __shfl_sync(0xffffffffu, gv, k);
            if (which == 0) {
                float2 xa = __half22float2(__ldg(xg + (size_t)sa * 16 + c2));
                ax0 = fmaf(ga, xa.x, ax0);
                ay0 = fmaf(ga, xa.y, ay0);
            }
        }
    }

    float ax = ax0 + ax1;
    float ay = ay0 + ay1;
    ax += __shfl_xor_sync(0xffffffffu, ax, 16);
    ay += __shfl_xor_sync(0xffffffffu, ay, 16);

    if (lane < 16) {
        float rinv = (deg > 0) ? (1.0f / (float)deg) : 0.0f;
        size_t o = (size_t)warp * 16 + c2;
        float2 r = __ldg(rootb + o);
        float2 ov;
        ov.x = ax * rinv + r.x;
        ov.y = ay * rinv + r.y;
        out[o] = ov;
    }
}

extern "C" void kernel_launch(void* const* d_in, const int* in_sizes, int n_in,
                              void* d_out, int out_size) {
    const int*   ei  = (const int*)d_in[0];
    const float* ew  = (const float*)d_in[1];
    const float* x   = (const float*)d_in[2];
    const float* g1  = (const float*)d_in[3];
    const float* mu1 = (const float*)d_in[4];
    const float* s1  = (const float*)d_in[5];
    const float* r1  = (const float*)d_in[6];
    const float* b1  = (const float*)d_in[7];
    const float* g2  = (const float*)d_in[8];
    const float* mu2 = (const float*)d_in[9];
    const float* s2  = (const float*)d_in[10];
    const float* r2  = (const float*)d_in[11];
    const float* b2  = (const float*)d_in[12];

    const int E = in_sizes[0] / 2;
    const int N = in_sizes[2] / 32;

    __half* xgh;
    float *rootb, *rootb2, *h;
    uint2* edges;
    int *cnt, *rowptr, *cursor, *bsum;
    cudaGetSymbolAddress((void**)&xgh, g_xgh);
    cudaGetSymbolAddress((void**)&rootb, g_rootb);
    cudaGetSymbolAddress((void**)&rootb2, g_rootb2);
    cudaGetSymbolAddress((void**)&h, g_h);
    cudaGetSymbolAddress((void**)&edges, g_edges);
    cudaGetSymbolAddress((void**)&cnt, g_cnt);
    cudaGetSymbolAddress((void**)&rowptr, g_rowptr);
    cudaGetSymbolAddress((void**)&cursor, g_cursor);
    cudaGetSymbolAddress((void**)&bsum, g_bsum);

    const int nb = (N + SCAN_BLK - 1) / SCAN_BLK;
    const int eb = (E + 255) / 256;
    const int gemm_blocks = (N + 127) / 128;
    const int pull_blocks = (N + 7) / 8;

    // ---- CSR build (shared by both layers) ----
    cudaMemsetAsync(cnt, 0, (size_t)N * sizeof(int), 0);
    hist_k<<<eb, 256>>>(ei, cnt, E);
    scan1_k<<<nb, SCAN_BLK>>>(cnt, rowptr, bsum, N);
    scan23_k<<<nb, SCAN_BLK>>>(rowptr, cursor, bsum, N, E);
    gau_scatter_k<<<eb, 256>>>(ei, (const float4*)ew, mu1, s1, mu2, s2, cursor, edges, E);

    // ---- layer 1 ----
    gemm_k<<<gemm_blocks, 256>>>(x, g1, r1, b1, xgh, rootb, N);
    pull_k<1><<<pull_blocks, 256>>>(rowptr, edges, (const __half2*)xgh,
                                    (const float2*)rootb, (float2*)h, N);

    // ---- layer 2 ----
    gemm_k<<<gemm_blocks, 256>>>(h, g2, r2, b2, xgh, rootb2, N);
    pull_k<2><<<pull_blocks, 256>>>(rowptr, edges, (const __half2*)xgh,
                                    (const float2*)rootb2, (float2*)d_out, N);
}

// round 15
// speedup vs baseline: 1.0492x; 1.0492x over previous
#include <cuda_runtime.h>
#include <cuda_fp16.h>
#include <cstdint>

// N=100000, E=1600000, D=8, K=1, C=32 (dims from in_sizes at runtime).
#define MAXN 100352
#define MAXE 1638400
#define SCAN_BLK 1024
#define MAX_SB 128   // max scan blocks (ceil(MAXN/1024) = 98)

__device__ __align__(16) __half g_xgh[MAXN * 32];    // x @ g (fp16 gather payload)
__device__ __align__(16) float g_rootb[MAXN * 32];   // root term (layer 1)
__device__ __align__(16) float g_rootb2[MAXN * 32];  // root term (layer 2)
__device__ __align__(16) float g_h[MAXN * 32];       // layer-1 output (fp32)
__device__ __align__(16) uint2 g_edges[MAXE];        // (src, half2(gau1,gau2)) sorted by dst
__device__ int g_cnt[MAXN];                           // in-degree histogram
__device__ int g_rowptr[MAXN + 1];                    // CSR row pointers (by dst)
__device__ int g_cursor[MAXN];                        // scatter cursors
__device__ int g_bsum[MAX_SB];                        // scan block sums

// ---------------- CSR build ----------------

__global__ void __launch_bounds__(256) hist_k(const int* __restrict__ ei, int* __restrict__ cnt, int E) {
    int e = blockIdx.x * blockDim.x + threadIdx.x;
    if (e < E) atomicAdd(cnt + __ldg(ei + E + e), 1);
}

// Per-block exclusive scan of 1024 counts; block totals to bsum.
__global__ void __launch_bounds__(SCAN_BLK) scan1_k(const int* __restrict__ cnt,
                                                    int* __restrict__ rowptr,
                                                    int* __restrict__ bsum, int N) {
    __shared__ int sh[SCAN_BLK];
    int t = threadIdx.x;
    int i = blockIdx.x * SCAN_BLK + t;
    int v = (i < N) ? cnt[i] : 0;
    sh[t] = v;
    __syncthreads();
    for (int off = 1; off < SCAN_BLK; off <<= 1) {
        int add = (t >= off) ? sh[t - off] : 0;
        __syncthreads();
        sh[t] += add;
        __syncthreads();
    }
    if (i < N) rowptr[i] = sh[t] - v;  // exclusive
    if (t == SCAN_BLK - 1) bsum[blockIdx.x] = sh[t];
}

// Fused scan2+scan3: each block computes its own block-offset (warp-reduced
// prefix over <=98 block sums), then applies it and initializes cursors.
__global__ void __launch_bounds__(SCAN_BLK) scan23_k(int* __restrict__ rowptr,
                                                     int* __restrict__ cursor,
                                                     const int* __restrict__ bsum,
                                                     int N, int E) {
    __shared__ int s_off;
    int t = threadIdx.x;
    if (t < 32) {
        int acc = 0;
        for (int j = t; j < blockIdx.x; j += 32) acc += __ldg(bsum + j);
        acc += __shfl_xor_sync(0xffffffffu, acc, 16);
        acc += __shfl_xor_sync(0xffffffffu, acc, 8);
        acc += __shfl_xor_sync(0xffffffffu, acc, 4);
        acc += __shfl_xor_sync(0xffffffffu, acc, 2);
        acc += __shfl_xor_sync(0xffffffffu, acc, 1);
        if (t == 0) s_off = acc;
    }
    __syncthreads();
    int i = blockIdx.x * SCAN_BLK + t;
    if (i < N) {
        int v = rowptr[i] + s_off;
        rowptr[i] = v;
        cursor[i] = v;
    }
    if (i == 0) rowptr[N] = E;
}

// Gaussian weights (both layers, packed half2) + scatter 8B records to the
// dst-sorted slot.
__global__ void __launch_bounds__(256) gau_scatter_k(
    const int* __restrict__ ei,
    const float4* __restrict__ ea,    // [E,8] viewed as [E,2] float4
    const float* __restrict__ mu1, const float* __restrict__ sg1,
    const float* __restrict__ mu2, const float* __restrict__ sg2,
    int* __restrict__ cursor,
    uint2* __restrict__ edges, int E) {
    int e = blockIdx.x * blockDim.x + threadIdx.x;
    if (e >= E) return;
    float4 a = ea[e * 2];
    float4 b = ea[e * 2 + 1];
    float v[8] = {a.x, a.y, a.z, a.w, b.x, b.y, b.z, b.w};
    float t1 = 0.f, t2 = 0.f;
#pragma unroll
    for (int d = 0; d < 8; d++) {
        float d1 = v[d] - __ldg(mu1 + d);
        float d2 = v[d] - __ldg(mu2 + d);
        t1 += (-0.5f * d1 * d1) / (1e-15f + __ldg(sg1 + d) * __ldg(sg1 + d));
        t2 += (-0.5f * d2 * d2) / (1e-15f + __ldg(sg2 + d) * __ldg(sg2 + d));
    }
    int src = __ldg(ei + e);
    int dst = __ldg(ei + E + e);
    int pos = atomicAdd(cursor + dst, 1);
    __half2 gp = __floats2half2_rn(__expf(t1), __expf(t2));
    uint2 rec;
    rec.x = (unsigned)src;
    rec.y = *reinterpret_cast<unsigned*>(&gp);
    edges[pos] = rec;
}

// ---------------- GEMM (register weights, fp16 xg output) ----------------

__global__ void __launch_bounds__(256) gemm_k(
    const float* __restrict__ xin,
    const float* __restrict__ g,
    const float* __restrict__ root,
    const float* __restrict__ bias,
    __half* __restrict__ xg,
    float* __restrict__ rb_out,
    int N) {
    __shared__ float sx[128][32];
    const int t = threadIdx.x;
    const int lane = t & 31;
    const int w = t >> 5;

    float wg[32], wr[32];
#pragma unroll
    for (int k = 0; k < 32; k++) {
        wg[k] = __ldg(g + k * 32 + lane);
        wr[k] = __ldg(root + k * 32 + lane);
    }
    const float bv = __ldg(bias + lane);

    const int base = blockIdx.x * 128;
    const int nrows = min(128, N - base);

    for (int i = t; i < nrows * 32; i += 256)
        sx[i >> 5][i & 31] = xin[(size_t)base * 32 + i];
    __syncthreads();

    for (int r = w; r < nrows; r += 8) {
        float a = 0.0f, b = bv;
#pragma unroll
        for (int k = 0; k < 32; k++) {
            float xv = sx[r][k];
            a = fmaf(xv, wg[k], a);
            b = fmaf(xv, wr[k], b);
        }
        size_t o = (size_t)(base + r) * 32 + lane;
        xg[o] = __float2half_rn(a);
        rb_out[o] = b;
    }
}

// ---------------- Pull aggregation: 2 edges per warp-instruction ----------------
// One warp per dst node. Lanes 0-15 process edge A, lanes 16-31 edge B; each
// lane owns 2 channels as one __half2 (4B load). Records loaded coalesced,
// redistributed via shfl; epilogue folds half-warps with shfl_xor(16).
template <int LAYER>
__global__ void __launch_bounds__(256) pull_k(
    const int* __restrict__ rowptr,
    const uint2* __restrict__ edges,
    const __half2* __restrict__ xg,   // [N,16] half2 rows
    const float2* __restrict__ rootb, // [N,16] float2 rows
    float2* __restrict__ out,         // [N,16] float2 rows
    int N) {
    int warp = (blockIdx.x * blockDim.x + threadIdx.x) >> 5;
    int lane = threadIdx.x & 31;
    if (warp >= N) return;

    const int c2 = lane & 15;     // channel-pair index (channels 2*c2, 2*c2+1)
    const int which = lane >> 4;  // 0 -> even edge, 1 -> odd edge

    int s = __ldg(rowptr + warp);
    int e = __ldg(rowptr + warp + 1);
    int deg = e - s;

    float ax0 = 0.f, ay0 = 0.f, ax1 = 0.f, ay1 = 0.f;

    for (int j = s; j < e; j += 32) {
        int m = min(32, e - j);
        // cooperative coalesced record load: lane i -> record j+i
        int   si = 0;
        float gv = 0.f;
        if (lane < m) {
            uint2 r = edges[j + lane];
            si = (int)r.x;
            __half2 gp = *reinterpret_cast<__half2*>(&r.y);
            gv = (LAYER == 1) ? __low2float(gp) : __high2float(gp);
        }
        int k = 0;
        for (; k + 4 <= m; k += 4) {
            int   sa = __shfl_sync(0xffffffffu, si, k + which);
            float ga = __shfl_sync(0xffffffffu, gv, k + which);
            int   sb = __shfl_sync(0xffffffffu, si, k + 2 + which);
            float gb = __shfl_sync(0xffffffffu, gv, k + 2 + which);
            float2 xa = __half22float2(__ldg(xg + (size_t)sa * 16 + c2));
            float2 xb = __half22float2(__ldg(xg + (size_t)sb * 16 + c2));
            ax0 = fmaf(ga, xa.x, ax0);
            ay0 = fmaf(ga, xa.y, ay0);
            ax1 = fmaf(gb, xb.x, ax1);
            ay1 = fmaf(gb, xb.y, ay1);
        }
        for (; k + 2 <= m; k += 2) {
            int   sa = __shfl_sync(0xffffffffu, si, k + which);
            float ga = __shfl_sync(0xffffffffu, gv, k + which);
            float2 xa = __half22float2(__ldg(xg + (size_t)sa * 16 + c2));
            ax0 = fmaf(ga, xa.x, ax0);
            ay0 = fmaf(ga, xa.y, ay0);
        }
        if (k < m) {  // single leftover edge: only the 'which==0' half contributes
            int   sa = __shfl_sync(0xffffffffu, si, k);
            float ga = __shfl_sync(0xffffffffu, gv, k);
            if (which == 0) {
                float2 xa = __half22float2(__ldg(xg + (size_t)sa * 16 + c2));
                ax0 = fmaf(ga, xa.x, ax0);
                ay0 = fmaf(ga, xa.y, ay0);
            }
        }
    }

    float ax = ax0 + ax1;
    float ay = ay0 + ay1;
    ax += __shfl_xor_sync(0xffffffffu, ax, 16);
    ay += __shfl_xor_sync(0xffffffffu, ay, 16);

    if (lane < 16) {
        float rinv = (deg > 0) ? (1.0f / (float)deg) : 0.0f;
        size_t o = (size_t)warp * 16 + c2;
        float2 r = __ldg(rootb + o);
        float2 ov;
        ov.x = ax * rinv + r.x;
        ov.y = ay * rinv + r.y;
        out[o] = ov;
    }
}

extern "C" void kernel_launch(void* const* d_in, const int* in_sizes, int n_in,
                              void* d_out, int out_size) {
    const int*   ei  = (const int*)d_in[0];
    const float* ew  = (const float*)d_in[1];
    const float* x   = (const float*)d_in[2];
    const float* g1  = (const float*)d_in[3];
    const float* mu1 = (const float*)d_in[4];
    const float* s1  = (const float*)d_in[5];
    const float* r1  = (const float*)d_in[6];
    const float* b1  = (const float*)d_in[7];
    const float* g2  = (const float*)d_in[8];
    const float* mu2 = (const float*)d_in[9];
    const float* s2  = (const float*)d_in[10];
    const float* r2  = (const float*)d_in[11];
    const float* b2  = (const float*)d_in[12];

    const int E = in_sizes[0] / 2;
    const int N = in_sizes[2] / 32;

    __half* xgh;
    float *rootb, *rootb2, *h;
    uint2* edges;
    int *cnt, *rowptr, *cursor, *bsum;
    cudaGetSymbolAddress((void**)&xgh, g_xgh);
    cudaGetSymbolAddress((void**)&rootb, g_rootb);
    cudaGetSymbolAddress((void**)&rootb2, g_rootb2);
    cudaGetSymbolAddress((void**)&h, g_h);
    cudaGetSymbolAddress((void**)&edges, g_edges);
    cudaGetSymbolAddress((void**)&cnt, g_cnt);
    cudaGetSymbolAddress((void**)&rowptr, g_rowptr);
    cudaGetSymbolAddress((void**)&cursor, g_cursor);
    cudaGetSymbolAddress((void**)&bsum, g_bsum);

    const int nb = (N + SCAN_BLK - 1) / SCAN_BLK;
    const int eb = (E + 255) / 256;
    const int gemm_blocks = (N + 127) / 128;
    const int pull_blocks = (N + 7) / 8;

    // Fork a non-blocking side stream: gemm1 (x@g1) is independent of the
    // CSR build chain, so it runs concurrently and its latency is hidden.
    cudaStream_t side;
    cudaEvent_t evFork, evJoin;
    cudaStreamCreateWithFlags(&side, cudaStreamNonBlocking);
    cudaEventCreateWithFlags(&evFork, cudaEventDisableTiming);
    cudaEventCreateWithFlags(&evJoin, cudaEventDisableTiming);

    cudaEventRecord(evFork, 0);
    cudaStreamWaitEvent(side, evFork, 0);
    gemm_k<<<gemm_blocks, 256, 0, side>>>(x, g1, r1, b1, xgh, rootb, N);
    cudaEventRecord(evJoin, side);

    // ---- CSR build (main stream, concurrent with gemm1) ----
    cudaMemsetAsync(cnt, 0, (size_t)N * sizeof(int), 0);
    hist_k<<<eb, 256>>>(ei, cnt, E);
    scan1_k<<<nb, SCAN_BLK>>>(cnt, rowptr, bsum, N);
    scan23_k<<<nb, SCAN_BLK>>>(rowptr, cursor, bsum, N, E);
    gau_scatter_k<<<eb, 256>>>(ei, (const float4*)ew, mu1, s1, mu2, s2, cursor, edges, E);

    // join: pull1 needs both the edge records and gemm1's outputs
    cudaStreamWaitEvent(0, evJoin, 0);

    // ---- layer 1 pull ----
    pull_k<1><<<pull_blocks, 256>>>(rowptr, edges, (const __half2*)xgh,
                                    (const float2*)rootb, (float2*)h, N);

    // ---- layer 2 ----
    gemm_k<<<gemm_blocks, 256>>>(h, g2, r2, b2, xgh, rootb2, N);
    pull_k<2><<<pull_blocks, 256>>>(rowptr, edges, (const __half2*)xgh,
                                    (const float2*)rootb2, (float2*)d_out, N);

    cudaEventDestroy(evFork);
    cudaEventDestroy(evJoin);
    cudaStreamDestroy(side);
}

// round 16
// speedup vs baseline: 1.0558x; 1.0063x over previous
#include <cuda_runtime.h>
#include <cuda_fp16.h>
#include <cstdint>

// N=100000, E=1600000, D=8, K=1, C=32 (dims from in_sizes at runtime).
#define MAXN 100352
#define MAXE 1638400
#define SCAN_BLK 1024
#define MAX_SB 128   // max scan blocks (ceil(MAXN/1024) = 98)

__device__ __align__(16) __half g_xgh[MAXN * 32];    // x @ g (fp16 gather payload)
__device__ __align__(16) float g_rootb[MAXN * 32];   // root term (layer 1)
__device__ __align__(16) float g_rootb2[MAXN * 32];  // root term (layer 2)
__device__ __align__(16) float g_h[MAXN * 32];       // layer-1 output (fp32)
__device__ __align__(16) uint2 g_edges[MAXE];        // (src, half2(gau1,gau2)) sorted by dst
__device__ int g_cnt[MAXN];                           // in-degree histogram
__device__ int g_rowptr[MAXN + 1];                    // CSR row pointers (by dst)
__device__ int g_cursor[MAXN];                        // scatter cursors
__device__ int g_bsum[MAX_SB];                        // scan block sums

// ---------------- CSR build ----------------

__global__ void __launch_bounds__(256) hist_k(const int* __restrict__ ei, int* __restrict__ cnt, int E) {
    int e = blockIdx.x * blockDim.x + threadIdx.x;
    if (e < E) atomicAdd(cnt + __ldg(ei + E + e), 1);
}

// Per-block exclusive scan of 1024 counts; block totals to bsum.
__global__ void __launch_bounds__(SCAN_BLK) scan1_k(const int* __restrict__ cnt,
                                                    int* __restrict__ rowptr,
                                                    int* __restrict__ bsum, int N) {
    __shared__ int sh[SCAN_BLK];
    int t = threadIdx.x;
    int i = blockIdx.x * SCAN_BLK + t;
    int v = (i < N) ? cnt[i] : 0;
    sh[t] = v;
    __syncthreads();
    for (int off = 1; off < SCAN_BLK; off <<= 1) {
        int add = (t >= off) ? sh[t - off] : 0;
        __syncthreads();
        sh[t] += add;
        __syncthreads();
    }
    if (i < N) rowptr[i] = sh[t] - v;  // exclusive
    if (t == SCAN_BLK - 1) bsum[blockIdx.x] = sh[t];
}

// Fused scan2+scan3: each block computes its own block-offset (warp-reduced
// prefix over <=98 block sums), then applies it and initializes cursors.
__global__ void __launch_bounds__(SCAN_BLK) scan23_k(int* __restrict__ rowptr,
                                                     int* __restrict__ cursor,
                                                     const int* __restrict__ bsum,
                                                     int N, int E) {
    __shared__ int s_off;
    int t = threadIdx.x;
    if (t < 32) {
        int acc = 0;
        for (int j = t; j < blockIdx.x; j += 32) acc += __ldg(bsum + j);
        acc += __shfl_xor_sync(0xffffffffu, acc, 16);
        acc += __shfl_xor_sync(0xffffffffu, acc, 8);
        acc += __shfl_xor_sync(0xffffffffu, acc, 4);
        acc += __shfl_xor_sync(0xffffffffu, acc, 2);
        acc += __shfl_xor_sync(0xffffffffu, acc, 1);
        if (t == 0) s_off = acc;
    }
    __syncthreads();
    int i = blockIdx.x * SCAN_BLK + t;
    if (i < N) {
        int v = rowptr[i] + s_off;
        rowptr[i] = v;
        cursor[i] = v;
    }
    if (i == 0) rowptr[N] = E;
}

// Gaussian weights (both layers, packed half2) + scatter 8B records to the
// dst-sorted slot.
__global__ void __launch_bounds__(256) gau_scatter_k(
    const int* __restrict__ ei,
    const float4* __restrict__ ea,    // [E,8] viewed as [E,2] float4
    const float* __restrict__ mu1, const float* __restrict__ sg1,
    const float* __restrict__ mu2, const float* __restrict__ sg2,
    int* __restrict__ cursor,
    uint2* __restrict__ edges, int E) {
    int e = blockIdx.x * blockDim.x + threadIdx.x;
    if (e >= E) return;
    float4 a = ea[e * 2];
    float4 b = ea[e * 2 + 1];
    float v[8] = {a.x, a.y, a.z, a.w, b.x, b.y, b.z, b.w};
    float t1 = 0.f, t2 = 0.f;
#pragma unroll
    for (int d = 0; d < 8; d++) {
        float d1 = v[d] - __ldg(mu1 + d);
        float d2 = v[d] - __ldg(mu2 + d);
        t1 += (-0.5f * d1 * d1) / (1e-15f + __ldg(sg1 + d) * __ldg(sg1 + d));
        t2 += (-0.5f * d2 * d2) / (1e-15f + __ldg(sg2 + d) * __ldg(sg2 + d));
    }
    int src = __ldg(ei + e);
    int dst = __ldg(ei + E + e);
    int pos = atomicAdd(cursor + dst, 1);
    __half2 gp = __floats2half2_rn(__expf(t1), __expf(t2));
    uint2 rec;
    rec.x = (unsigned)src;
    rec.y = *reinterpret_cast<unsigned*>(&gp);
    edges[pos] = rec;
}

// ---------------- GEMM (register weights, fp16 xg output) ----------------

__global__ void __launch_bounds__(256) gemm_k(
    const float* __restrict__ xin,
    const float* __restrict__ g,
    const float* __restrict__ root,
    const float* __restrict__ bias,
    __half* __restrict__ xg,
    float* __restrict__ rb_out,
    int N) {
    __shared__ float sx[128][32];
    const int t = threadIdx.x;
    const int lane = t & 31;
    const int w = t >> 5;

    float wg[32], wr[32];
#pragma unroll
    for (int k = 0; k < 32; k++) {
        wg[k] = __ldg(g + k * 32 + lane);
        wr[k] = __ldg(root + k * 32 + lane);
    }
    const float bv = __ldg(bias + lane);

    const int base = blockIdx.x * 128;
    const int nrows = min(128, N - base);

    for (int i = t; i < nrows * 32; i += 256)
        sx[i >> 5][i & 31] = xin[(size_t)base * 32 + i];
    __syncthreads();

    for (int r = w; r < nrows; r += 8) {
        float a = 0.0f, b = bv;
#pragma unroll
        for (int k = 0; k < 32; k++) {
            float xv = sx[r][k];
            a = fmaf(xv, wg[k], a);
            b = fmaf(xv, wr[k], b);
        }
        size_t o = (size_t)(base + r) * 32 + lane;
        xg[o] = __float2half_rn(a);
        rb_out[o] = b;
    }
}

// ---------------- Pull aggregation: 4 edges per warp-instruction ----------------
// One warp per dst node. Lane = 8*which + c4: 'which' (0..3) selects the edge
// within a 4-edge group, c4 (0..7) selects 4 channels loaded as one uint2
// (2x half2, 8B). Per 4-edge group: 2 shfl pairs + 1 load + 4 FMA per lane.
// Dual accumulator banks (groups k, k+4) preserve MLP. Remainder is
// branch-free: out-of-range lanes get gau=0 and re-load group-0's row (same
// cache line). Epilogue folds with shfl_xor(8)+shfl_xor(16); lanes 0-7 write
// one float4 each (coalesced 128B row).
template <int LAYER>
__global__ void __launch_bounds__(256) pull_k(
    const int* __restrict__ rowptr,
    const uint2* __restrict__ edges,
    const uint2* __restrict__ xg,     // [N,8] uint2 rows (32 fp16 channels)
    const float4* __restrict__ rootb, // [N,8] float4 rows
    float4* __restrict__ out,         // [N,8] float4 rows
    int N) {
    int warp = (blockIdx.x * blockDim.x + threadIdx.x) >> 5;
    int lane = threadIdx.x & 31;
    if (warp >= N) return;

    const int c4 = lane & 7;      // channel quad (channels 4*c4 .. 4*c4+3)
    const int which = lane >> 3;  // edge slot within a 4-edge group

    int s = __ldg(rowptr + warp);
    int e = __ldg(rowptr + warp + 1);
    int deg = e - s;

    float a0 = 0.f, a1 = 0.f, a2 = 0.f, a3 = 0.f;   // bank A
    float b0 = 0.f, b1 = 0.f, b2 = 0.f, b3 = 0.f;   // bank B

    for (int j = s; j < e; j += 32) {
        int m = min(32, e - j);
        // cooperative coalesced record load: lane i -> record j+i
        int   si = 0;
        float gv = 0.f;
        if (lane < m) {
            uint2 r = edges[j + lane];
            si = (int)r.x;
            __half2 gp = *reinterpret_cast<__half2*>(&r.y);
            gv = (LAYER == 1) ? __low2float(gp) : __high2float(gp);
        }
        int k = 0;
        for (; k + 8 <= m; k += 8) {
            int   sa = __shfl_sync(0xffffffffu, si, k + which);
            float ga = __shfl_sync(0xffffffffu, gv, k + which);
            int   sb = __shfl_sync(0xffffffffu, si, k + 4 + which);
            float gb = __shfl_sync(0xffffffffu, gv, k + 4 + which);
            uint2 ua = __ldg(xg + (size_t)sa * 8 + c4);
            uint2 ub = __ldg(xg + (size_t)sb * 8 + c4);
            float2 xa0 = __half22float2(*reinterpret_cast<__half2*>(&ua.x));
            float2 xa1 = __half22float2(*reinterpret_cast<__half2*>(&ua.y));
            float2 xb0 = __half22float2(*reinterpret_cast<__half2*>(&ub.x));
            float2 xb1 = __half22float2(*reinterpret_cast<__half2*>(&ub.y));
            a0 = fmaf(ga, xa0.x, a0); a1 = fmaf(ga, xa0.y, a1);
            a2 = fmaf(ga, xa1.x, a2); a3 = fmaf(ga, xa1.y, a3);
            b0 = fmaf(gb, xb0.x, b0); b1 = fmaf(gb, xb0.y, b1);
            b2 = fmaf(gb, xb1.x, b2); b3 = fmaf(gb, xb1.y, b3);
        }
        if (k + 4 <= m) {
            int   sa = __shfl_sync(0xffffffffu, si, k + which);
            float ga = __shfl_sync(0xffffffffu, gv, k + which);
            uint2 ua = __ldg(xg + (size_t)sa * 8 + c4);
            float2 xa0 = __half22float2(*reinterpret_cast<__half2*>(&ua.x));
            float2 xa1 = __half22float2(*reinterpret_cast<__half2*>(&ua.y));
            a0 = fmaf(ga, xa0.x, a0); a1 = fmaf(ga, xa0.y, a1);
            a2 = fmaf(ga, xa1.x, a2); a3 = fmaf(ga, xa1.y, a3);
            k += 4;
        }
        int rem = m - k;  // 0..3
        if (rem > 0) {
            int idx = k + (which < rem ? which : 0);
            int   sa = __shfl_sync(0xffffffffu, si, idx);
            float ga = __shfl_sync(0xffffffffu, gv, idx);
            ga = (which < rem) ? ga : 0.f;  // padded lanes contribute 0
            uint2 ua = __ldg(xg + (size_t)sa * 8 + c4);
            float2 xa0 = __half22float2(*reinterpret_cast<__half2*>(&ua.x));
            float2 xa1 = __half22float2(*reinterpret_cast<__half2*>(&ua.y));
            a0 = fmaf(ga, xa0.x, a0); a1 = fmaf(ga, xa0.y, a1);
            a2 = fmaf(ga, xa1.x, a2); a3 = fmaf(ga, xa1.y, a3);
        }
    }

    a0 += b0; a1 += b1; a2 += b2; a3 += b3;
    a0 += __shfl_xor_sync(0xffffffffu, a0, 8);
    a1 += __shfl_xor_sync(0xffffffffu, a1, 8);
    a2 += __shfl_xor_sync(0xffffffffu, a2, 8);
    a3 += __shfl_xor_sync(0xffffffffu, a3, 8);
    a0 += __shfl_xor_sync(0xffffffffu, a0, 16);
    a1 += __shfl_xor_sync(0xffffffffu, a1, 16);
    a2 += __shfl_xor_sync(0xffffffffu, a2, 16);
    a3 += __shfl_xor_sync(0xffffffffu, a3, 16);

    if (lane < 8) {
        float rinv = (deg > 0) ? (1.0f / (float)deg) : 0.0f;
        size_t o = (size_t)warp * 8 + c4;
        float4 rb = __ldg(rootb + o);
        float4 ov;
        ov.x = a0 * rinv + rb.x;
        ov.y = a1 * rinv + rb.y;
        ov.z = a2 * rinv + rb.z;
        ov.w = a3 * rinv + rb.w;
        out[o] = ov;
    }
}

extern "C" void kernel_launch(void* const* d_in, const int* in_sizes, int n_in,
                              void* d_out, int out_size) {
    const int*   ei  = (const int*)d_in[0];
    const float* ew  = (const float*)d_in[1];
    const float* x   = (const float*)d_in[2];
    const float* g1  = (const float*)d_in[3];
    const float* mu1 = (const float*)d_in[4];
    const float* s1  = (const float*)d_in[5];
    const float* r1  = (const float*)d_in[6];
    const float* b1  = (const float*)d_in[7];
    const float* g2  = (const float*)d_in[8];
    const float* mu2 = (const float*)d_in[9];
    const float* s2  = (const float*)d_in[10];
    const float* r2  = (const float*)d_in[11];
    const float* b2  = (const float*)d_in[12];

    const int E = in_sizes[0] / 2;
    const int N = in_sizes[2] / 32;

    __half* xgh;
    float *rootb, *rootb2, *h;
    uint2* edges;
    int *cnt, *rowptr, *cursor, *bsum;
    cudaGetSymbolAddress((void**)&xgh, g_xgh);
    cudaGetSymbolAddress((void**)&rootb, g_rootb);
    cudaGetSymbolAddress((void**)&rootb2, g_rootb2);
    cudaGetSymbolAddress((void**)&h, g_h);
    cudaGetSymbolAddress((void**)&edges, g_edges);
    cudaGetSymbolAddress((void**)&cnt, g_cnt);
    cudaGetSymbolAddress((void**)&rowptr, g_rowptr);
    cudaGetSymbolAddress((void**)&cursor, g_cursor);
    cudaGetSymbolAddress((void**)&bsum, g_bsum);

    const int nb = (N + SCAN_BLK - 1) / SCAN_BLK;
    const int eb = (E + 255) / 256;
    const int gemm_blocks = (N + 127) / 128;
    const int pull_blocks = (N + 7) / 8;

    // Fork a non-blocking side stream: gemm1 (x@g1) is independent of the
    // CSR build chain, so it runs concurrently and its latency is hidden.
    cudaStream_t side;
    cudaEvent_t evFork, evJoin;
    cudaStreamCreateWithFlags(&side, cudaStreamNonBlocking);
    cudaEventCreateWithFlags(&evFork, cudaEventDisableTiming);
    cudaEventCreateWithFlags(&evJoin, cudaEventDisableTiming);

    cudaEventRecord(evFork, 0);
    cudaStreamWaitEvent(side, evFork, 0);
    gemm_k<<<gemm_blocks, 256, 0, side>>>(x, g1, r1, b1, xgh, rootb, N);
    cudaEventRecord(evJoin, side);

    // ---- CSR build (main stream, concurrent with gemm1) ----
    cudaMemsetAsync(cnt, 0, (size_t)N * sizeof(int), 0);
    hist_k<<<eb, 256>>>(ei, cnt, E);
    scan1_k<<<nb, SCAN_BLK>>>(cnt, rowptr, bsum, N);
    scan23_k<<<nb, SCAN_BLK>>>(rowptr, cursor, bsum, N, E);
    gau_scatter_k<<<eb, 256>>>(ei, (const float4*)ew, mu1, s1, mu2, s2, cursor, edges, E);

    // join: pull1 needs both the edge records and gemm1's outputs
    cudaStreamWaitEvent(0, evJoin, 0);

    // ---- layer 1 pull ----
    pull_k<1><<<pull_blocks, 256>>>(rowptr, edges, (const uint2*)xgh,
                                    (const float4*)rootb, (float4*)h, N);

    // ---- layer 2 ----
    gemm_k<<<gemm_blocks, 256>>>(h, g2, r2, b2, xgh, rootb2, N);
    pull_k<2><<<pull_blocks, 256>>>(rowptr, edges, (const uint2*)xgh,
                                    (const float4*)rootb2, (float4*)d_out, N);

    cudaEventDestroy(evFork);
    cudaEventDestroy(evJoin);
    cudaStreamDestroy(side);
}